// round 11
// baseline (speedup 1.0000x reference)
#include <cuda_runtime.h>

#define HH 512
#define WW 512
#define HW (512*512)
#define NB 16
#define HISTX 14

// Scratch (static device memory)
__device__ unsigned char g_code[32 * HW];   // bit0=m0, bit1=m1, bit2=m4 (plane=side*16+b)
__device__ unsigned char g_tmp8[32 * HW];   // horizontal 25-max of (m2+m3), 0..2
__device__ unsigned char g_mse8[NB * HW];   // expanded eye mask (source), 0..2
__device__ unsigned char g_mre8[NB * HW];   // expanded eye mask (ref), 0..2
__device__ int   g_hist[NB * 24 * 256];     // [(match*2+side)*3 + c]*256 + bin
__device__ float g_tabf[NB * 12 * 256];     // pre-converted to renorm space

__device__ __forceinline__ float denorm255(float x) {
    return fminf(fmaxf((x + 1.0f) * 0.5f, 0.0f), 1.0f) * 255.0f;
}
__device__ __forceinline__ float fcomp(const float4& v, int p) {
    return p == 0 ? v.x : (p == 1 ? v.y : (p == 2 ? v.z : v.w));
}

// Reads all 5 mask planes once: emits code byte + horizontal 25-max of (m2+m3).
// Also zeroes g_hist (replay-safe).
__global__ void k_prep(const float* __restrict__ ms, const float* __restrict__ mr) {
    int t = threadIdx.x;  // 0..127
    if (blockIdx.y == 0 && blockIdx.x < 192) {
        ((int4*)g_hist)[blockIdx.x * 128 + t] = make_int4(0, 0, 0, 0);
    }
    int plane = blockIdx.y;
    int b = plane & 15;
    const float* base = ((plane < 16) ? ms : mr) + (size_t)b * 5 * HW;
    int y = blockIdx.x;
    const float4* p0 = (const float4*)(base + 0 * HW + y * WW);
    const float4* p1 = (const float4*)(base + 1 * HW + y * WW);
    const float4* p2 = (const float4*)(base + 2 * HW + y * WW);
    const float4* p3 = (const float4*)(base + 3 * HW + y * WW);
    const float4* p4 = (const float4*)(base + 4 * HW + y * WW);
    float4 v0 = p0[t], v1 = p1[t], v2 = p2[t], v3 = p3[t], v4 = p4[t];
    uchar4 code;
    code.x = (v0.x > 0.f) | ((v1.x > 0.f) << 1) | ((v4.x > 0.f) << 2);
    code.y = (v0.y > 0.f) | ((v1.y > 0.f) << 1) | ((v4.y > 0.f) << 2);
    code.z = (v0.z > 0.f) | ((v1.z > 0.f) << 1) | ((v4.z > 0.f) << 2);
    code.w = (v0.w > 0.f) | ((v1.w > 0.f) << 1) | ((v4.w > 0.f) << 2);
    *(uchar4*)(g_code + (size_t)plane * HW + y * WW + t * 4) = code;

    __shared__ float srow[536];
    *(float4*)&srow[12 + t * 4] =
        make_float4(v2.x + v3.x, v2.y + v3.y, v2.z + v3.z, v2.w + v3.w);
    if (t < 12) { srow[t] = 0.0f; srow[524 + t] = 0.0f; }
    __syncthreads();
    int x0 = t * 4;
    float common = srow[x0 + 3];
#pragma unroll
    for (int j = 4; j <= 24; j++) common = fmaxf(common, srow[x0 + j]);
    uchar4 o;
    o.x = (unsigned char)fmaxf(fmaxf(srow[x0], srow[x0 + 1]), fmaxf(srow[x0 + 2], common));
    o.y = (unsigned char)fmaxf(fmaxf(srow[x0 + 1], srow[x0 + 2]), fmaxf(common, srow[x0 + 25]));
    o.z = (unsigned char)fmaxf(fmaxf(srow[x0 + 2], common), fmaxf(srow[x0 + 25], srow[x0 + 26]));
    o.w = (unsigned char)fmaxf(fmaxf(common, srow[x0 + 25]), fmaxf(srow[x0 + 26], srow[x0 + 27]));
    *(uchar4*)(g_tmp8 + (size_t)plane * HW + y * WW + x0) = o;
}

// Vertical 25-tall max of g_tmp8, gated by m1 bit in code -> g_mse8 / g_mre8
__global__ void k_colmax() {
    int plane = blockIdx.z;
    int b = plane & 15;
    int x0 = blockIdx.x * 32, y0 = blockIdx.y * 32;
    __shared__ unsigned char t[56][32];
    int tid = threadIdx.x;  // 256 threads
    for (int j = tid; j < 448; j += 256) {
        int ry = j >> 3, cx = (j & 7) * 4;
        int y = y0 - 12 + ry;
        uchar4 v = make_uchar4(0, 0, 0, 0);
        if (y >= 0 && y < HH)
            v = *(const uchar4*)(g_tmp8 + (size_t)plane * HW + y * WW + x0 + cx);
        *(uchar4*)&t[ry][cx] = v;
    }
    __syncthreads();
    int tx = tid & 31;
    int oy = (tid >> 5) * 4;
    int common = t[oy + 3][tx];
#pragma unroll
    for (int j = 4; j <= 24; j++) common = max(common, (int)t[oy + j][tx]);
    int o0 = max(max((int)t[oy][tx], (int)t[oy + 1][tx]), max((int)t[oy + 2][tx], common));
    int o1 = max(max((int)t[oy + 1][tx], (int)t[oy + 2][tx]), max(common, (int)t[oy + 25][tx]));
    int o2 = max(max((int)t[oy + 2][tx], common), max((int)t[oy + 25][tx], (int)t[oy + 26][tx]));
    int o3 = max(max(common, (int)t[oy + 25][tx]), max((int)t[oy + 26][tx], (int)t[oy + 27][tx]));
    unsigned char* dst = ((plane < 16) ? g_mse8 : g_mre8) + (size_t)b * HW;
    const unsigned char* cd = g_code + (size_t)plane * HW;
    int ov[4] = { o0, o1, o2, o3 };
#pragma unroll
    for (int r = 0; r < 4; r++) {
        int pix = (y0 + oy + r) * WW + x0 + tx;
        dst[pix] = (cd[pix] & 2) ? (unsigned char)ov[r] : 0;
    }
}

// Code-combined histograms: ONE atomic per (pixel,channel) for all 3 binary masks.
__global__ void k_hist(const float* __restrict__ src, const float* __restrict__ tgt) {
    __shared__ int shc[6144];  // [code(8)][ch(3)][bin(256)]
    __shared__ int she[768];   // eye: [ch(3)][bin(256)]
    int tid = threadIdx.x;
    for (int j = tid; j < 6144; j += 512) shc[j] = 0;
    for (int j = tid; j < 768; j += 512) she[j] = 0;
    __syncthreads();
    int side = blockIdx.z;
    int b = blockIdx.y;
    const float4* img = (const float4*)((side ? tgt : src) + (size_t)b * 3 * HW);
    const uchar4* cd  = (const uchar4*)(g_code + (size_t)((side << 4) | b) * HW);
    const uchar4* ey  = (const uchar4*)((side ? g_mre8 : g_mse8) + (size_t)b * HW);
    const int Q = HW / 4;

    for (int i = blockIdx.x * 512 + tid; i < Q; i += HISTX * 512) {
        float4 v0 = img[i], v1 = img[Q + i], v2 = img[2 * Q + i];
        uchar4 c4 = cd[i], e4 = ey[i];
        unsigned char cv[4] = { c4.x, c4.y, c4.z, c4.w };
        unsigned char ev[4] = { e4.x, e4.y, e4.z, e4.w };
#pragma unroll
        for (int p = 0; p < 4; p++) {
            float d0 = denorm255(fcomp(v0, p));
            float d1 = denorm255(fcomp(v1, p));
            float d2 = denorm255(fcomp(v2, p));
            int code = cv[p];
            if (code) {
                int base = code * 768;
                atomicAdd(&shc[base + (int)d0], 1);
                atomicAdd(&shc[base + 256 + (int)d1], 1);
                atomicAdd(&shc[base + 512 + (int)d2], 1);
            }
            int w = ev[p];
            if (w == 2) {
                atomicAdd(&she[      min((int)(d0 * 2.0f), 255)], 2);
                atomicAdd(&she[256 + min((int)(d1 * 2.0f), 255)], 2);
                atomicAdd(&she[512 + min((int)(d2 * 2.0f), 255)], 2);
            } else if (w == 1) {
                atomicAdd(&she[      (int)d0], 1);
                atomicAdd(&she[256 + (int)d1], 1);
                atomicAdd(&she[512 + (int)d2], 1);
            }
        }
    }
    __syncthreads();
    int* gh = g_hist + b * 6144;
    for (int j = tid; j < 3072; j += 512) {
        int match = j / 768, r = j - match * 768;
        int v;
        if (match == 0)      v = shc[2*768+r] + shc[3*768+r] + shc[6*768+r] + shc[7*768+r];
        else if (match == 1) v = shc[4*768+r] + shc[5*768+r] + shc[6*768+r] + shc[7*768+r];
        else if (match == 2) v = shc[1*768+r] + shc[3*768+r] + shc[5*768+r] + shc[7*768+r];
        else                 v = she[r];
        if (v) atomicAdd(&gh[(match * 2 + side) * 768 + r], v);
    }
}

// cumsum (warp-shuffle scan) -> cdf -> searchsorted(left) -> float table
__global__ void k_table() {
    int b = blockIdx.y;
    int match = blockIdx.x / 3, c = blockIdx.x % 3;
    int i = threadIdx.x;
    int lane = i & 31, wid = i >> 5;
    const int* hb = g_hist + b * 6144;
    int vs = hb[(match * 2 + 0) * 768 + c * 256 + i];
    int vr = hb[(match * 2 + 1) * 768 + c * 256 + i];
#pragma unroll
    for (int off = 1; off < 32; off <<= 1) {
        int ts = __shfl_up_sync(0xffffffffu, vs, off);
        int tr = __shfl_up_sync(0xffffffffu, vr, off);
        if (lane >= off) { vs += ts; vr += tr; }
    }
    __shared__ int wsumS[8], wsumR[8];
    if (lane == 31) { wsumS[wid] = vs; wsumR[wid] = vr; }
    __syncthreads();
    if (wid == 0 && lane < 8) {
        int a = wsumS[lane], bb = wsumR[lane];
#pragma unroll
        for (int off = 1; off < 8; off <<= 1) {
            int ta = __shfl_up_sync(0xffu, a, off);
            int tb = __shfl_up_sync(0xffu, bb, off);
            if (lane >= off) { a += ta; bb += tb; }
        }
        wsumS[lane] = a; wsumR[lane] = bb;
    }
    __syncthreads();
    if (wid > 0) { vs += wsumS[wid - 1]; vr += wsumR[wid - 1]; }
    float totS = (float)wsumS[7], totR = (float)wsumR[7];
    float cs = (float)vs / fmaxf(totS, 1e-6f);
    __shared__ float cdfR[256];
    cdfR[i] = (float)vr / fmaxf(totR, 1e-6f);
    __syncthreads();
    int lo = 0, hi = 256;
    while (lo < hi) {
        int mid = (lo + hi) >> 1;
        if (cdfR[mid] < cs) lo = mid + 1; else hi = mid;
    }
    float t = (float)min(lo, 255);
    g_tabf[((b * 4 + match) * 3 + c) * 256 + i] = (t / 255.0f) * 2.0f - 1.0f;
}

// Final fused compose: 256 threads, TWO independent pixel-groups per thread,
// all global loads issued up-front (high per-thread MLP).
#define SMP 136   // shared pitch (bytes), interior at offset 4
__global__ void k_compose(const float* __restrict__ src, const float* __restrict__ tgt,
                          float* __restrict__ out) {
    const int b = blockIdx.z;
    const int x0 = blockIdx.x * 128, y0 = blockIdx.y * 16;
    __shared__ float stab[3072];
    __shared__ unsigned char smse[20 * SMP];
    __shared__ unsigned char svs[16 * SMP];   // vertical 5-sums
    const int tid = threadIdx.x;  // 256
    for (int j = tid; j < 3072; j += 256) stab[j] = g_tabf[b * 3072 + j];
    for (int j = tid; j < 20 * SMP; j += 256) {
        int ry = j / SMP, cx = j - (j / SMP) * SMP;
        int y = y0 - 2 + ry, x = x0 - 4 + cx;
        unsigned char v = 0;
        if (y >= 0 && y < HH && x >= 0 && x < WW) v = g_mse8[(size_t)b * HW + y * WW + x];
        smse[j] = v;
    }
    __syncthreads();
    for (int j = tid; j < 16 * SMP; j += 256) {
        int ry = j / SMP, cx = j - (j / SMP) * SMP;
        svs[j] = smse[ry * SMP + cx] + smse[(ry + 1) * SMP + cx] + smse[(ry + 2) * SMP + cx]
               + smse[(ry + 3) * SMP + cx] + smse[(ry + 4) * SMP + cx];
    }
    __syncthreads();
    const float4* is = (const float4*)(src + (size_t)b * 3 * HW);
    const float4* ir = (const float4*)(tgt + (size_t)b * 3 * HW);
    const uchar4* cd = (const uchar4*)(g_code + (size_t)b * HW);
    float4* ob = (float4*)(out + (size_t)b * 3 * HW);
    const unsigned int* smseu = (const unsigned int*)smse;
    const unsigned int* svsu  = (const unsigned int*)svs;
    const int Q = HW / 4;

    // two independent groups per thread: rows rA and rA+8
    const int rA = tid >> 5, rB = rA + 8;
    const int col4 = (tid & 31) << 2;
    const int iA = ((y0 + rA) * WW + x0 + col4) >> 2;
    const int iB = ((y0 + rB) * WW + x0 + col4) >> 2;

    // ---- issue ALL global loads up front ----
    uchar4 cA = cd[iA],  cB = cd[iB];
    float4 aA0 = is[iA], aA1 = is[Q + iA], aA2 = is[2 * Q + iA];
    float4 aB0 = is[iB], aB1 = is[Q + iB], aB2 = is[2 * Q + iB];
    float4 rA0 = ir[iA], rA1 = ir[Q + iA], rA2 = ir[2 * Q + iA];
    float4 rB0 = ir[iB], rB1 = ir[Q + iB], rB2 = ir[2 * Q + iB];

#pragma unroll
    for (int g = 0; g < 2; g++) {
        const int row = g ? rB : rA;
        const int i4  = g ? iB : iA;
        uchar4 c4 = g ? cB : cA;
        float4 a0 = g ? aB0 : aA0, a1 = g ? aB1 : aA1, a2 = g ? aB2 : aA2;
        float4 r0 = g ? rB0 : rA0, r1 = g ? rB1 : rA1, r2 = g ? rB2 : rA2;
        unsigned char cv[4] = { c4.x, c4.y, c4.z, c4.w };
        unsigned int mctr = smseu[(row + 2) * (SMP / 4) + (col4 >> 2) + 1];
        unsigned int u0 = 0, u1 = 0, u2 = 0;
        if (mctr) {
            int base = row * (SMP / 4) + (col4 >> 2);
            u0 = svsu[base]; u1 = svsu[base + 1]; u2 = svsu[base + 2];
        }
        float4 o0, o1, o2;
        float* po0 = &o0.x; float* po1 = &o1.x; float* po2 = &o2.x;
#pragma unroll
        for (int p = 0; p < 4; p++) {
            int code = cv[p];
            int msei = (mctr >> (8 * p)) & 255;
            float mse = (float)msei;
            float A = 1.0f - 0.8f * mse;
            if (code & 2) A *= 0.7f;
            if (code & 1) A *= 0.9f;
            float Bc = 1.0f - A;
            int tbase = (code & 1) ? 1536 : ((code & 4) ? 768 : 0);
            float mb = 0.0f;
            if (msei > 0) {
                int s = 0;
#pragma unroll
                for (int q = 0; q < 5; q++) {
                    int bi = 2 + p + q;
                    unsigned int uu = (bi < 4) ? u0 : ((bi < 8) ? u1 : u2);
                    s += (uu >> (8 * (bi & 3))) & 255;
                }
                mb = ((float)s / 25.0f) * mse;
            }
            float av[3] = { fcomp(a0, p), fcomp(a1, p), fcomp(a2, p) };
            float rv[3] = { fcomp(r0, p), fcomp(r1, p), fcomp(r2, p) };
            float pv[3];
#pragma unroll
            for (int c = 0; c < 3; c++) {
                float a = av[c];
                float d = denorm255(a);
                int bi = (int)d;
                float pgt = code ? stab[tbase + c * 256 + bi] : a;
                if (msei > 0) {
                    int be = (msei == 1) ? bi : min((int)(d + d), 255);
                    float xm = stab[2304 + c * 256 + be];
                    pgt = (1.0f - mb) * pgt + mb * xm;
                }
                pv[c] = A * pgt + Bc * rv[c];
            }
            po0[p] = pv[0]; po1[p] = pv[1]; po2[p] = pv[2];
        }
        ob[i4] = o0; ob[Q + i4] = o1; ob[2 * Q + i4] = o2;
    }
}

extern "C" void kernel_launch(void* const* d_in, const int* in_sizes, int n_in,
                              void* d_out, int out_size) {
    const float* src = (const float*)d_in[0];
    const float* tgt = (const float*)d_in[1];
    const float* ms  = (const float*)d_in[2];
    const float* mr  = (const float*)d_in[3];
    float* out = (float*)d_out;

    k_prep<<<dim3(512, 32), 128>>>(ms, mr);
    k_colmax<<<dim3(16, 16, 32), 256>>>();
    k_hist<<<dim3(HISTX, 16, 2), 512>>>(src, tgt);
    k_table<<<dim3(12, 16), 256>>>();
    k_compose<<<dim3(4, 32, 16), 256>>>(src, tgt, out);
}

// round 12
// speedup vs baseline: 1.1454x; 1.1454x over previous
#include <cuda_runtime.h>

#define HH 512
#define WW 512
#define HW (512*512)
#define NB 16
#define HISTX 14

// Scratch (static device memory)
__device__ unsigned char g_code[32 * HW];   // bit0=m0, bit1=m1, bit2=m4 (plane=side*16+b)
__device__ unsigned char g_tmp8[32 * HW];   // horizontal 25-max of (m2+m3), 0..2
__device__ unsigned char g_mse8[NB * HW];   // expanded+gated eye mask (source)
__device__ unsigned char g_mre8[NB * HW];   // expanded+gated eye mask (ref)
__device__ unsigned char g_blur8[NB * HW];  // 5x5 sum of g_mse8 (0..50)
__device__ int   g_hist[NB * 24 * 256];     // [(match*2+side)*3 + c]*256 + bin
__device__ float g_tabf[NB * 12 * 256];     // pre-converted to renorm space

__device__ __forceinline__ float denorm255(float x) {
    return fminf(fmaxf((x + 1.0f) * 0.5f, 0.0f), 1.0f) * 255.0f;
}
__device__ __forceinline__ float fcomp(const float4& v, int p) {
    return p == 0 ? v.x : (p == 1 ? v.y : (p == 2 ? v.z : v.w));
}

// Reads all 5 mask planes once: emits code byte + horizontal 25-max of (m2+m3).
// Also zeroes g_hist (replay-safe).
__global__ void k_prep(const float* __restrict__ ms, const float* __restrict__ mr) {
    int t = threadIdx.x;  // 0..127
    if (blockIdx.y == 0 && blockIdx.x < 192) {
        ((int4*)g_hist)[blockIdx.x * 128 + t] = make_int4(0, 0, 0, 0);
    }
    int plane = blockIdx.y;
    int b = plane & 15;
    const float* base = ((plane < 16) ? ms : mr) + (size_t)b * 5 * HW;
    int y = blockIdx.x;
    const float4* p0 = (const float4*)(base + 0 * HW + y * WW);
    const float4* p1 = (const float4*)(base + 1 * HW + y * WW);
    const float4* p2 = (const float4*)(base + 2 * HW + y * WW);
    const float4* p3 = (const float4*)(base + 3 * HW + y * WW);
    const float4* p4 = (const float4*)(base + 4 * HW + y * WW);
    float4 v0 = p0[t], v1 = p1[t], v2 = p2[t], v3 = p3[t], v4 = p4[t];
    uchar4 code;
    code.x = (v0.x > 0.f) | ((v1.x > 0.f) << 1) | ((v4.x > 0.f) << 2);
    code.y = (v0.y > 0.f) | ((v1.y > 0.f) << 1) | ((v4.y > 0.f) << 2);
    code.z = (v0.z > 0.f) | ((v1.z > 0.f) << 1) | ((v4.z > 0.f) << 2);
    code.w = (v0.w > 0.f) | ((v1.w > 0.f) << 1) | ((v4.w > 0.f) << 2);
    *(uchar4*)(g_code + (size_t)plane * HW + y * WW + t * 4) = code;

    __shared__ float srow[536];
    *(float4*)&srow[12 + t * 4] =
        make_float4(v2.x + v3.x, v2.y + v3.y, v2.z + v3.z, v2.w + v3.w);
    if (t < 12) { srow[t] = 0.0f; srow[524 + t] = 0.0f; }
    __syncthreads();
    int x0 = t * 4;
    float common = srow[x0 + 3];
#pragma unroll
    for (int j = 4; j <= 24; j++) common = fmaxf(common, srow[x0 + j]);
    uchar4 o;
    o.x = (unsigned char)fmaxf(fmaxf(srow[x0], srow[x0 + 1]), fmaxf(srow[x0 + 2], common));
    o.y = (unsigned char)fmaxf(fmaxf(srow[x0 + 1], srow[x0 + 2]), fmaxf(common, srow[x0 + 25]));
    o.z = (unsigned char)fmaxf(fmaxf(srow[x0 + 2], common), fmaxf(srow[x0 + 25], srow[x0 + 26]));
    o.w = (unsigned char)fmaxf(fmaxf(common, srow[x0 + 25]), fmaxf(srow[x0 + 26], srow[x0 + 27]));
    *(uchar4*)(g_tmp8 + (size_t)plane * HW + y * WW + x0) = o;
}

// Vertical 25-max + gate; source side additionally computes the 5x5 blur sum.
__global__ void k_colmax() {
    int plane = blockIdx.z;
    int b = plane & 15;
    int x0 = blockIdx.x * 32, y0 = blockIdx.y * 32;
    __shared__ unsigned char tmp[60 * 40];   // rows y0-14..y0+45, cols x0-4..x0+35
    __shared__ unsigned char mse[36 * 40];   // rows y0-2..y0+33,  cols x0-2..x0+33
    __shared__ unsigned char vsum[32 * 40];  // vertical 5-sums
    int tid = threadIdx.x;  // 256
    // A: load tmp8 halo tile
    for (int j = tid; j < 600; j += 256) {
        int r = j / 10, q = j - (j / 10) * 10;
        int y = y0 - 14 + r, x = x0 - 4 + q * 4;
        unsigned int v = 0;
        if (y >= 0 && y < HH && x >= 0 && x < WW)
            v = *(const unsigned int*)(g_tmp8 + (size_t)plane * HW + y * WW + x);
        *(unsigned int*)&tmp[r * 40 + q * 4] = v;
    }
    __syncthreads();
    // B: vertical 25-max (common-interior trick, 4 rows/task) + code gating
    const unsigned char* cdp = g_code + (size_t)plane * HW;
    for (int j = tid; j < 324; j += 256) {
        int g = j / 36, c = j - (j / 36) * 36;
        int tc = c + 2;
        int base = 4 * g;
        int common = tmp[(base + 3) * 40 + tc];
#pragma unroll
        for (int k = 4; k <= 24; k++) common = max(common, (int)tmp[(base + k) * 40 + tc]);
        int t0 = tmp[base * 40 + tc], t1 = tmp[(base + 1) * 40 + tc], t2 = tmp[(base + 2) * 40 + tc];
        int t25 = tmp[(base + 25) * 40 + tc], t26 = tmp[(base + 26) * 40 + tc], t27 = tmp[(base + 27) * 40 + tc];
        int ov[4];
        ov[0] = max(max(t0, t1), max(t2, common));
        ov[1] = max(max(t1, t2), max(common, t25));
        ov[2] = max(max(t2, common), max(t25, t26));
        ov[3] = max(max(common, t25), max(t26, t27));
        int x = x0 - 2 + c;
#pragma unroll
        for (int r = 0; r < 4; r++) {
            int y = y0 - 2 + base + r;
            int val = 0;
            if (y >= 0 && y < HH && x >= 0 && x < WW && (cdp[y * WW + x] & 2)) val = ov[r];
            mse[(base + r) * 40 + c] = (unsigned char)val;
        }
    }
    __syncthreads();
    if (plane < 16) {
        // C: vertical 5-sums
        for (int j = tid; j < 1152; j += 256) {
            int r = j / 36, c = j - (j / 36) * 36;
            vsum[r * 40 + c] = mse[r * 40 + c] + mse[(r + 1) * 40 + c] + mse[(r + 2) * 40 + c]
                             + mse[(r + 3) * 40 + c] + mse[(r + 4) * 40 + c];
        }
        __syncthreads();
        // D: write mse + blur (one uchar4 pair per thread)
        int r = tid >> 3, c4 = (tid & 7) * 4;
        uchar4 mo, bo;
        unsigned char* pm = &mo.x; unsigned char* pb = &bo.x;
#pragma unroll
        for (int k = 0; k < 4; k++) {
            int c = c4 + k;
            pm[k] = mse[(r + 2) * 40 + c + 2];
            int s = vsum[r * 40 + c] + vsum[r * 40 + c + 1] + vsum[r * 40 + c + 2]
                  + vsum[r * 40 + c + 3] + vsum[r * 40 + c + 4];
            pb[k] = (unsigned char)s;
        }
        int pix = (y0 + r) * WW + x0 + c4;
        *(uchar4*)(g_mse8  + (size_t)b * HW + pix) = mo;
        *(uchar4*)(g_blur8 + (size_t)b * HW + pix) = bo;
    } else {
        int r = tid >> 3, c4 = (tid & 7) * 4;
        uchar4 mo; unsigned char* pm = &mo.x;
#pragma unroll
        for (int k = 0; k < 4; k++) pm[k] = mse[(r + 2) * 40 + c4 + k + 2];
        *(uchar4*)(g_mre8 + (size_t)b * HW + (y0 + r) * WW + x0 + c4) = mo;
    }
}

// Code-combined histograms: ONE atomic per (pixel,channel) for all 3 binary masks.
__global__ void k_hist(const float* __restrict__ src, const float* __restrict__ tgt) {
    __shared__ int shc[6144];  // [code(8)][ch(3)][bin(256)]
    __shared__ int she[768];   // eye: [ch(3)][bin(256)]
    int tid = threadIdx.x;
    for (int j = tid; j < 6144; j += 512) shc[j] = 0;
    for (int j = tid; j < 768; j += 512) she[j] = 0;
    __syncthreads();
    int side = blockIdx.z;
    int b = blockIdx.y;
    const float4* img = (const float4*)((side ? tgt : src) + (size_t)b * 3 * HW);
    const uchar4* cd  = (const uchar4*)(g_code + (size_t)((side << 4) | b) * HW);
    const uchar4* ey  = (const uchar4*)((side ? g_mre8 : g_mse8) + (size_t)b * HW);
    const int Q = HW / 4;

    for (int i = blockIdx.x * 512 + tid; i < Q; i += HISTX * 512) {
        float4 v0 = img[i], v1 = img[Q + i], v2 = img[2 * Q + i];
        uchar4 c4 = cd[i], e4 = ey[i];
        unsigned char cv[4] = { c4.x, c4.y, c4.z, c4.w };
        unsigned char ev[4] = { e4.x, e4.y, e4.z, e4.w };
#pragma unroll
        for (int p = 0; p < 4; p++) {
            float d0 = denorm255(fcomp(v0, p));
            float d1 = denorm255(fcomp(v1, p));
            float d2 = denorm255(fcomp(v2, p));
            int code = cv[p];
            if (code) {
                int base = code * 768;
                atomicAdd(&shc[base + (int)d0], 1);
                atomicAdd(&shc[base + 256 + (int)d1], 1);
                atomicAdd(&shc[base + 512 + (int)d2], 1);
            }
            int w = ev[p];
            if (w == 2) {
                atomicAdd(&she[      min((int)(d0 * 2.0f), 255)], 2);
                atomicAdd(&she[256 + min((int)(d1 * 2.0f), 255)], 2);
                atomicAdd(&she[512 + min((int)(d2 * 2.0f), 255)], 2);
            } else if (w == 1) {
                atomicAdd(&she[      (int)d0], 1);
                atomicAdd(&she[256 + (int)d1], 1);
                atomicAdd(&she[512 + (int)d2], 1);
            }
        }
    }
    __syncthreads();
    int* gh = g_hist + b * 6144;
    for (int j = tid; j < 3072; j += 512) {
        int match = j / 768, r = j - match * 768;
        int v;
        if (match == 0)      v = shc[2*768+r] + shc[3*768+r] + shc[6*768+r] + shc[7*768+r];
        else if (match == 1) v = shc[4*768+r] + shc[5*768+r] + shc[6*768+r] + shc[7*768+r];
        else if (match == 2) v = shc[1*768+r] + shc[3*768+r] + shc[5*768+r] + shc[7*768+r];
        else                 v = she[r];
        if (v) atomicAdd(&gh[(match * 2 + side) * 768 + r], v);
    }
}

// cumsum (warp-shuffle scan) -> cdf -> searchsorted(left) -> float table
__global__ void k_table() {
    int b = blockIdx.y;
    int match = blockIdx.x / 3, c = blockIdx.x % 3;
    int i = threadIdx.x;
    int lane = i & 31, wid = i >> 5;
    const int* hb = g_hist + b * 6144;
    int vs = hb[(match * 2 + 0) * 768 + c * 256 + i];
    int vr = hb[(match * 2 + 1) * 768 + c * 256 + i];
#pragma unroll
    for (int off = 1; off < 32; off <<= 1) {
        int ts = __shfl_up_sync(0xffffffffu, vs, off);
        int tr = __shfl_up_sync(0xffffffffu, vr, off);
        if (lane >= off) { vs += ts; vr += tr; }
    }
    __shared__ int wsumS[8], wsumR[8];
    if (lane == 31) { wsumS[wid] = vs; wsumR[wid] = vr; }
    __syncthreads();
    if (wid == 0 && lane < 8) {
        int a = wsumS[lane], bb = wsumR[lane];
#pragma unroll
        for (int off = 1; off < 8; off <<= 1) {
            int ta = __shfl_up_sync(0xffu, a, off);
            int tb = __shfl_up_sync(0xffu, bb, off);
            if (lane >= off) { a += ta; bb += tb; }
        }
        wsumS[lane] = a; wsumR[lane] = bb;
    }
    __syncthreads();
    if (wid > 0) { vs += wsumS[wid - 1]; vr += wsumR[wid - 1]; }
    float totS = (float)wsumS[7], totR = (float)wsumR[7];
    float cs = (float)vs / fmaxf(totS, 1e-6f);
    __shared__ float cdfR[256];
    cdfR[i] = (float)vr / fmaxf(totR, 1e-6f);
    __syncthreads();
    int lo = 0, hi = 256;
    while (lo < hi) {
        int mid = (lo + hi) >> 1;
        if (cdfR[mid] < cs) lo = mid + 1; else hi = mid;
    }
    float t = (float)min(lo, 255);
    g_tabf[((b * 4 + match) * 3 + c) * 256 + i] = (t / 255.0f) * 2.0f - 1.0f;
}

// Final fused compose: flat streaming kernel, no spatial tiles, no blur LDS.
__global__ void k_compose(const float* __restrict__ src, const float* __restrict__ tgt,
                          float* __restrict__ out) {
    const int b = blockIdx.y;
    __shared__ float stab[3072];
    const int tid = threadIdx.x;  // 512
    for (int j = tid; j < 3072; j += 512) stab[j] = g_tabf[b * 3072 + j];
    __syncthreads();
    const float4* is = (const float4*)(src + (size_t)b * 3 * HW);
    const float4* ir = (const float4*)(tgt + (size_t)b * 3 * HW);
    const uchar4* cd = (const uchar4*)(g_code  + (size_t)b * HW);
    const uchar4* me = (const uchar4*)(g_mse8  + (size_t)b * HW);
    const uchar4* bl = (const uchar4*)(g_blur8 + (size_t)b * HW);
    float4* ob = (float4*)(out + (size_t)b * 3 * HW);
    const int Q = HW / 4;

    const int i4 = blockIdx.x * 512 + tid;   // gridDim.x*512 == Q
    uchar4 c4 = cd[i4], m4 = me[i4], b4 = bl[i4];
    unsigned char cv[4] = { c4.x, c4.y, c4.z, c4.w };
    unsigned char mv[4] = { m4.x, m4.y, m4.z, m4.w };
    unsigned char bv[4] = { b4.x, b4.y, b4.z, b4.w };
    float4 a0 = is[i4], a1 = is[Q + i4], a2 = is[2 * Q + i4];
    float4 r0 = ir[i4], r1 = ir[Q + i4], r2 = ir[2 * Q + i4];
    float4 o0, o1, o2;
    float* po0 = &o0.x; float* po1 = &o1.x; float* po2 = &o2.x;
#pragma unroll
    for (int p = 0; p < 4; p++) {
        int code = cv[p];
        int msei = mv[p];
        float mse = (float)msei;
        float A = 1.0f - 0.8f * mse;
        if (code & 2) A *= 0.7f;
        if (code & 1) A *= 0.9f;
        float Bc = 1.0f - A;
        int tbase = (code & 1) ? 1536 : ((code & 4) ? 768 : 0);
        float mb = ((float)bv[p] / 25.0f) * mse;
        float av[3] = { fcomp(a0, p), fcomp(a1, p), fcomp(a2, p) };
        float rv[3] = { fcomp(r0, p), fcomp(r1, p), fcomp(r2, p) };
        float pv[3];
#pragma unroll
        for (int c = 0; c < 3; c++) {
            float a = av[c];
            float d = denorm255(a);
            int bi = (int)d;
            float pgt = code ? stab[tbase + c * 256 + bi] : a;
            if (msei > 0) {
                int be = (msei == 1) ? bi : min((int)(d + d), 255);
                float xm = stab[2304 + c * 256 + be];
                pgt = (1.0f - mb) * pgt + mb * xm;
            }
            pv[c] = A * pgt + Bc * rv[c];
        }
        po0[p] = pv[0]; po1[p] = pv[1]; po2[p] = pv[2];
    }
    ob[i4] = o0; ob[Q + i4] = o1; ob[2 * Q + i4] = o2;
}

extern "C" void kernel_launch(void* const* d_in, const int* in_sizes, int n_in,
                              void* d_out, int out_size) {
    const float* src = (const float*)d_in[0];
    const float* tgt = (const float*)d_in[1];
    const float* ms  = (const float*)d_in[2];
    const float* mr  = (const float*)d_in[3];
    float* out = (float*)d_out;

    k_prep<<<dim3(512, 32), 128>>>(ms, mr);
    k_colmax<<<dim3(16, 16, 32), 256>>>();
    k_hist<<<dim3(HISTX, 16, 2), 512>>>(src, tgt);
    k_table<<<dim3(12, 16), 256>>>();
    k_compose<<<dim3(128, 16), 512>>>(src, tgt, out);
}